// round 7
// baseline (speedup 1.0000x reference)
#include <cuda_runtime.h>
#include <cstdint>
#include <math.h>

#define BB   64
#define HH   128
#define NT   4096
#define EE   131072
#define KK   52
#define NK   3328
#define NEG  0.01f

// ---------------- shared memory layout (float offsets) ----------------
#define SM_M    0          // 4096  M[c*64+r] = A_d[r][c]
#define SM_S    4096       // 4096  S[r*64+c]
#define SM_X    8192       // 8192  x (64x128)
#define SM_Q    16384      // 8192  q (xq / qt / xq2)
#define SM_AXC  24576      // 8192  a(att1) -> h2 -> xc -> h2(att2)
#define SM_H1   32768      // 16384 h1 (64x256); also a(att2)@+0, apq@+8192, tmp/agg@+0, T@+0
#define SM_MISC 49152
#define MS_DEG   0
#define MS_DINV  64
#define MS_FOWN  128
#define MS_FPEER 192
#define MS_GOWN  256
#define MS_GPEER 320
#define MS_SCORE 384
#define MS_RED   448       // 256 floats
#define MS_PERM  704       // 64 ints
#define MS_CNT   768       // 2048 ints (packed 2x uint16)
#define SM_STG  (SM_MISC + 768 + 2048)   // 4096-float weight staging ring
#define SM_TOTALF (SM_STG + 4096)
#define SM_BYTES  (SM_TOTALF * 4)

#define NTHR 256

__device__ __forceinline__ float leaky(float v) { return v > 0.0f ? v : NEG * v; }

// ---- packed fp32 (fma.rn.f32x2) ----
__device__ __forceinline__ unsigned long long packf2(float f) {
    unsigned long long d; unsigned int u = __float_as_uint(f);
    asm("mov.b64 %0, {%1, %1};" : "=l"(d) : "r"(u));
    return d;
}
__device__ __forceinline__ void fma2(unsigned long long& acc,
                                     unsigned long long a, unsigned long long b) {
    asm("fma.rn.f32x2 %0, %1, %2, %0;" : "+l"(acc) : "l"(a), "l"(b));
}
__device__ __forceinline__ void unpackf2(unsigned long long v, float& lo, float& hi) {
    unsigned int ul, uh;
    asm("mov.b64 {%0, %1}, %2;" : "=r"(ul), "=r"(uh) : "l"(v));
    lo = __uint_as_float(ul); hi = __uint_as_float(uh);
}

// ---- cluster helpers ----
__device__ __forceinline__ void cluster_sync() {
    asm volatile("barrier.cluster.arrive.aligned;" ::: "memory");
    asm volatile("barrier.cluster.wait.aligned;" ::: "memory");
}
__device__ __forceinline__ float dsread(const float* p, unsigned peer) {
    unsigned addr = (unsigned)__cvta_generic_to_shared((void*)p);
    unsigned ra; float v;
    asm volatile("mapa.shared::cluster.u32 %0, %1, %2;" : "=r"(ra) : "r"(addr), "r"(peer));
    asm volatile("ld.shared::cluster.f32 %0, [%1];" : "=f"(v) : "r"(ra));
    return v;
}

// ---- GEMM microkernel: C[64 x N], 8 warps, thread tile 8 rows x (2*JN) cols
// A in smem (float4 along k), W in smem (staged), f32x2 accum.
template<int JN>
__device__ __forceinline__ void gseg(const float* __restrict__ As, int ldA,
                                     const float* __restrict__ W, int wld, int K,
                                     int ty, int txc, unsigned long long acc[8][JN]) {
    const float* a0 = As + ty * 8 * ldA;
    const float* wbase = W + txc * (2 * JN);
    for (int k = 0; k < K; k += 4) {
        float4 av[8];
        #pragma unroll
        for (int r = 0; r < 8; r++) av[r] = *(const float4*)(a0 + r * ldA + k);
        #pragma unroll
        for (int kk = 0; kk < 4; kk++) {
            const ulonglong2* wp = (const ulonglong2*)(wbase + (size_t)(k + kk) * wld);
            unsigned long long b2[JN];
            { ulonglong2 p0 = wp[0]; b2[0] = p0.x; b2[1] = p0.y; }
            if (JN == 4) { ulonglong2 p1 = wp[1]; b2[2] = p1.x; b2[3] = p1.y; }
            #pragma unroll
            for (int r = 0; r < 8; r++) {
                float aval = kk == 0 ? av[r].x : kk == 1 ? av[r].y : kk == 2 ? av[r].z : av[r].w;
                unsigned long long a2 = packf2(aval);
                #pragma unroll
                for (int j = 0; j < JN; j++) fma2(acc[r][j], a2, b2[j]);
            }
        }
    }
}

// Transposed-A variant for agg: A[c][k] = S[k*64+c]
template<int JN>
__device__ __forceinline__ void gsegT(const float* __restrict__ S,
                                      const float* __restrict__ W, int wld, int K,
                                      int ty, int txc, unsigned long long acc[8][JN]) {
    int c0 = ty * 8;
    const float* wbase = W + txc * (2 * JN);
    for (int k = 0; k < K; k++) {
        const ulonglong2* wp = (const ulonglong2*)(wbase + (size_t)k * wld);
        unsigned long long b2[JN];
        { ulonglong2 p0 = wp[0]; b2[0] = p0.x; b2[1] = p0.y; }
        if (JN == 4) { ulonglong2 p1 = wp[1]; b2[2] = p1.x; b2[3] = p1.y; }
        #pragma unroll
        for (int r = 0; r < 8; r++) {
            unsigned long long a2 = packf2(S[k * 64 + c0 + r]);
            #pragma unroll
            for (int j = 0; j < JN; j++) fma2(acc[r][j], a2, b2[j]);
        }
    }
}

template<int JN, int ACT>
__device__ __forceinline__ void estore(float* C, int ldC, int ty, int txc,
                                       unsigned long long acc[8][JN]) {
    #pragma unroll
    for (int r = 0; r < 8; r++) {
        float* crow = C + (ty * 8 + r) * ldC + txc * (2 * JN);
        #pragma unroll
        for (int j = 0; j < JN; j++) {
            float lo, hi; unpackf2(acc[r][j], lo, hi);
            if (ACT == 1) { lo = leaky(lo); hi = leaky(hi); }
            ((float2*)crow)[j] = make_float2(lo, hi);
        }
    }
}

// ---- staged GEMM: weights from GLOBAL, staged chunk-wise through smem ----
// Each chunk (4096 floats) is LDG'd once per CTA (prefetched into regs,
// overlapped with compute of previous chunk), then LDS-broadcast to all warps.
template<int JN>
__device__ __forceinline__ void gstaged(const float* __restrict__ As, int ldA,
    const float* __restrict__ Wg, int wld, int K, float* stg,
    int t, int ty, int txc, unsigned long long acc[8][JN]) {
    const int chunkK = 4096 / wld;
    float4 pf[4];
    {
        const float4* wg4 = (const float4*)Wg;
        #pragma unroll
        for (int i = 0; i < 4; i++) pf[i] = wg4[t + i * 256];
    }
    for (int c0 = 0; c0 < K; c0 += chunkK) {
        #pragma unroll
        for (int i = 0; i < 4; i++) *(float4*)(stg + 4 * (t + i * 256)) = pf[i];
        __syncthreads();
        if (c0 + chunkK < K) {
            const float4* wg4 = (const float4*)(Wg + (size_t)(c0 + chunkK) * wld);
            #pragma unroll
            for (int i = 0; i < 4; i++) pf[i] = wg4[t + i * 256];
        }
        gseg<JN>(As + c0, ldA, stg, wld, chunkK, ty, txc, acc);
        __syncthreads();
    }
}

// ---- staged GEMM with on-the-fly W1 fold (wld=256, K=128, chunk=16) ------
// OP: 0 -> W0+W1p, 1 -> W0-W1p, 2 -> W0 only
template<int OP, int JN>
__device__ __forceinline__ void gstagedF(const float* __restrict__ As, int ldA,
    const float* __restrict__ W0, const float* __restrict__ W1p, float* stg,
    int t, int ty, int txc, unsigned long long acc[8][JN]) {
    const int chunkK = 16, wld = 256, K = 128;
    float4 p0[4], p1[4];
    {
        const float4* a4 = (const float4*)W0;
        #pragma unroll
        for (int i = 0; i < 4; i++) p0[i] = a4[t + i * 256];
        if (OP < 2) {
            const float4* b4 = (const float4*)W1p;
            #pragma unroll
            for (int i = 0; i < 4; i++) p1[i] = b4[t + i * 256];
        }
    }
    for (int c0 = 0; c0 < K; c0 += chunkK) {
        #pragma unroll
        for (int i = 0; i < 4; i++) {
            float4 v = p0[i];
            if (OP == 0) { v.x += p1[i].x; v.y += p1[i].y; v.z += p1[i].z; v.w += p1[i].w; }
            if (OP == 1) { v.x -= p1[i].x; v.y -= p1[i].y; v.z -= p1[i].z; v.w -= p1[i].w; }
            *(float4*)(stg + 4 * (t + i * 256)) = v;
        }
        __syncthreads();
        if (c0 + chunkK < K) {
            const float4* a4 = (const float4*)(W0 + (size_t)(c0 + chunkK) * wld);
            #pragma unroll
            for (int i = 0; i < 4; i++) p0[i] = a4[t + i * 256];
            if (OP < 2) {
                const float4* b4 = (const float4*)(W1p + (size_t)(c0 + chunkK) * wld);
                #pragma unroll
                for (int i = 0; i < 4; i++) p1[i] = b4[t + i * 256];
            }
        }
        gseg<JN>(As + c0, ldA, stg, wld, chunkK, ty, txc, acc);
        __syncthreads();
    }
}

// ---- in-place softmax over v[0..63]; red scratch; all 256 threads ----
__device__ void softmax64(float* v, float* red, int t) {
    if (t < 64) red[t] = v[t];
    __syncthreads();
    for (int o = 32; o; o >>= 1) { if (t < o) red[t] = fmaxf(red[t], red[t + o]); __syncthreads(); }
    float m = red[0];
    __syncthreads();
    if (t < 64) { float e = expf(v[t] - m); v[t] = e; red[t] = e; }
    __syncthreads();
    for (int o = 32; o; o >>= 1) { if (t < o) red[t] += red[t + o]; __syncthreads(); }
    float d = red[0];
    __syncthreads();
    if (t < 64) v[t] = v[t] / d;
    __syncthreads();
}

// ---- full attention branch: fout = segsoftmax(leaky(MLP(kv, q))) ----------
__device__ void attention(float* sm, int t, int ty, int txc,
                          const float* kv, const float* q, float* aDest,
                          int head, const float* Wk, const float* W1,
                          const float* W2, const float* W3, float* fout) {
    float* red = sm + SM_MISC + MS_RED;
    float* stg = sm + SM_STG;
    float* apq = sm + SM_H1 + 8192;
    float* h1  = sm + SM_H1;
    float* h2  = sm + SM_AXC;

    // a = kv @ Wk[head]   (staged)
    {
        unsigned long long acc[8][2];
        #pragma unroll
        for (int r = 0; r < 8; r++) { acc[r][0] = 0ull; acc[r][1] = 0ull; }
        gstaged<2>(kv, 128, Wk + head * 16384, 128, 128, stg, t, ty, txc, acc);
        estore<2, 0>(aDest, 128, ty, txc, acc);
    }
    __syncthreads();
    // apq = a * q
    for (int i = t * 4; i < 8192; i += NTHR * 4) {
        float4 av = *(const float4*)(aDest + i);
        float4 qv = *(const float4*)(q + i);
        *(float4*)(apq + i) = make_float4(av.x * qv.x, av.y * qv.y, av.z * qv.z, av.w * qv.w);
    }
    __syncthreads();
    // h1 = leaky([a,q,a*q] @ folded(W1[head]))   K=3x128, folded on the fly
    {
        unsigned long long acc[8][4];
        #pragma unroll
        for (int r = 0; r < 8; r++)
            #pragma unroll
            for (int j = 0; j < 4; j++) acc[r][j] = 0ull;
        const float* W1h = W1 + (size_t)head * 512 * 256;
        gstagedF<0, 4>(aDest, 128, W1h,             W1h + 256 * 256, stg, t, ty, txc, acc);
        gstagedF<1, 4>(q,     128, W1h + 128 * 256, W1h + 256 * 256, stg, t, ty, txc, acc);
        gstagedF<2, 4>(apq,   128, W1h + 384 * 256, nullptr,         stg, t, ty, txc, acc);
        estore<4, 1>(h1, 256, ty, txc, acc);   // last gstagedF ended with sync
    }
    __syncthreads();
    // h2 = leaky(h1 @ W2[head])   (staged)
    {
        unsigned long long acc[8][2];
        #pragma unroll
        for (int r = 0; r < 8; r++) { acc[r][0] = 0ull; acc[r][1] = 0ull; }
        gstaged<2>(h1, 256, W2 + head * 32768, 128, 256, stg, t, ty, txc, acc);
        estore<2, 1>(h2, 128, ty, txc, acc);
    }
    __syncthreads();
    // logit = leaky(h2 @ W3[head]); softmax over 64. 4 partials per row.
    {
        int row = t >> 2, part = t & 3;
        const float4* hp = (const float4*)(h2 + row * 128 + part * 32);
        const float4* wp = (const float4*)(W3 + head * 128 + part * 32);
        float s = 0.0f;
        #pragma unroll
        for (int i = 0; i < 8; i++) {
            float4 a = hp[i], b = wp[i];
            s += a.x * b.x + a.y * b.y + a.z * b.z + a.w * b.w;
        }
        red[t] = s;
    }
    __syncthreads();
    if (t < 64) fout[t] = leaky(red[t * 4] + red[t * 4 + 1] + red[t * 4 + 2] + red[t * 4 + 3]);
    __syncthreads();
    softmax64(fout, red, t);
}

// ---------------- THE mega kernel: one cluster = one batch -----------------
extern __shared__ float sm[];

__global__ void __launch_bounds__(NTHR, 1) __cluster_dims__(2, 1, 1)
mega_k(const float* __restrict__ xg, const int* __restrict__ ei,
       const float* __restrict__ ew, const float* __restrict__ tx,
       const float* __restrict__ Wk, const float* __restrict__ W1,
       const float* __restrict__ W2, const float* __restrict__ W3,
       const float* __restrict__ lW,
       float* __restrict__ outx, float* __restrict__ outA2,
       float* __restrict__ outb, float* __restrict__ outp) {
    int t = threadIdx.x;
    int ty = t >> 5, txc = t & 31;
    int b = blockIdx.x >> 1;
    unsigned rank = blockIdx.x & 1;

    float* Ms    = sm + SM_M;
    float* Ss    = sm + SM_S;
    float* xs    = sm + SM_X;
    float* qs    = sm + SM_Q;
    float* axc   = sm + SM_AXC;
    float* h1b   = sm + SM_H1;
    float* degs  = sm + SM_MISC + MS_DEG;
    float* dinvs = sm + SM_MISC + MS_DINV;
    float* fown  = sm + SM_MISC + MS_FOWN;
    float* fpeer = sm + SM_MISC + MS_FPEER;
    float* gown  = sm + SM_MISC + MS_GOWN;
    float* gpeer = sm + SM_MISC + MS_GPEER;
    float* sscore= sm + SM_MISC + MS_SCORE;
    float* red   = sm + SM_MISC + MS_RED;
    int*   permsh= (int*)(sm + SM_MISC + MS_PERM);
    int*   cw    = (int*)(sm + SM_MISC + MS_CNT);

    // ---- zero this CTA's A2 row-strip (26 rows x NK); overlaps with compute
    {
        float4 z = make_float4(0.0f, 0.0f, 0.0f, 0.0f);
        float4* dst = (float4*)(outA2 + ((size_t)b * KK + rank * 26) * NK);
        for (int i = t; i < 26 * NK / 4; i += NTHR) dst[i] = z;
    }

    // ---- stage 0: load x, init, build deg/dinv/M/Cnt ----
    for (int i = t; i < 4096; i += NTHR) Ms[i] = 0.0f;
    for (int i = t; i < 2048; i += NTHR) cw[i] = 0;
    if (t < 64) degs[t] = 1.0f;     // self-loop weight
    for (int i = t * 4; i < 8192; i += NTHR * 4)
        *(float4*)(xs + i) = *(const float4*)(xg + (size_t)b * 8192 + i);
    __syncthreads();

    int er[8], ec[8]; float ewv[8];
    #pragma unroll
    for (int u = 0; u < 8; u++) {
        int e = b * 2048 + t + u * NTHR;
        er[u] = ei[e] - b * 64;
        ec[u] = ei[EE + e] - b * 64;
        ewv[u] = ew[e];
        atomicAdd(&degs[ec[u]], ewv[u]);
    }
    __syncthreads();
    if (t < 64) {
        float d = degs[t];
        dinvs[t] = d > 0.0f ? (1.0f / sqrtf(fmaxf(d, 1e-12f))) : 0.0f;
    }
    __syncthreads();
    #pragma unroll
    for (int u = 0; u < 8; u++) {
        atomicAdd(&Ms[ec[u] * 64 + er[u]], dinvs[er[u]] * ewv[u] * dinvs[ec[u]]);
        atomicAdd(&cw[(er[u] * 64 + ec[u]) >> 1], 1 << ((ec[u] & 1) * 16));
    }
    if (t < 64) {
        float dv = dinvs[t];
        atomicAdd(&Ms[t * 64 + t], dv * dv);
        atomicAdd(&cw[(t * 64 + t) >> 1], 1 << ((t & 1) * 16));
    }
    __syncthreads();

    // ---- stage 1: q = hop2(x) for rank0, q = broadcast target for rank1 ----
    if (rank == 0) {
        float* tmp = h1b;
        unsigned long long acc[8][2];
        #pragma unroll
        for (int r = 0; r < 8; r++) { acc[r][0] = 0ull; acc[r][1] = 0ull; }
        gseg<2>(Ms, 64, xs, 128, 64, ty, txc, acc);
        estore<2, 0>(tmp, 128, ty, txc, acc);
        __syncthreads();
        unsigned long long acc2[8][2];
        #pragma unroll
        for (int r = 0; r < 8; r++) { acc2[r][0] = 0ull; acc2[r][1] = 0ull; }
        gseg<2>(Ms, 64, tmp, 128, 64, ty, txc, acc2);
        estore<2, 0>(qs, 128, ty, txc, acc2);
    } else {
        for (int i = t * 4; i < 8192; i += NTHR * 4)
            *(float4*)(qs + i) = *(const float4*)(tx + b * 128 + (i & 127));
    }
    __syncthreads();

    // ---- stage 2: attention #1 (head = rank) -> fown ----
    attention(sm, t, ty, txc, xs, qs, axc, (int)rank, Wk, W1, W2, W3, fown);

    // exchange f with peer CTA
    cluster_sync();
    if (t < 64) fpeer[t] = dsread(fown + t, rank ^ 1);
    __syncthreads();

    // ---- stage 3: build S (edge softmax, count-weighted), 4 partials/col ----
    {
        const float* f1 = rank ? fpeer : fown;
        const float* f2 = rank ? fown : fpeer;
        int c = t >> 2, rq = t & 3;
        float f1c = f1[c];
        float mx = -3.0e38f;
        for (int r = rq * 16; r < rq * 16 + 16; r++) {
            int cnt = (cw[(r * 64 + c) >> 1] >> ((c & 1) * 16)) & 0xffff;
            if (cnt) mx = fmaxf(mx, leaky(f1c + f2[r]));
        }
        red[t] = mx; __syncthreads();
        mx = fmaxf(fmaxf(red[c * 4], red[c * 4 + 1]), fmaxf(red[c * 4 + 2], red[c * 4 + 3]));
        __syncthreads();
        float dp = 0.0f;
        for (int r = rq * 16; r < rq * 16 + 16; r++) {
            int cnt = (cw[(r * 64 + c) >> 1] >> ((c & 1) * 16)) & 0xffff;
            float e = 0.0f;
            if (cnt) e = (float)cnt * expf(leaky(f1c + f2[r]) - mx);
            Ss[r * 64 + c] = e; dp += e;
        }
        red[t] = dp; __syncthreads();
        float inv = 1.0f / (red[c * 4] + red[c * 4 + 1] + red[c * 4 + 2] + red[c * 4 + 3]);
        for (int r = rq * 16; r < rq * 16 + 16; r++) Ss[r * 64 + c] *= inv;
        __syncthreads();
    }

    // ---- stage 4: agg = S^T x ; x_c = mean_h leaky(x + agg @ lW[h]) ----
    float* agg = h1b;
    {
        unsigned long long acc[8][2];
        #pragma unroll
        for (int r = 0; r < 8; r++) { acc[r][0] = 0ull; acc[r][1] = 0ull; }
        gsegT<2>(Ss, xs, 128, 64, ty, txc, acc);
        estore<2, 0>(agg, 128, ty, txc, acc);
    }
    __syncthreads();
    {
        float* stg = sm + SM_STG;
        unsigned long long a0[8][2], a1[8][2];
        #pragma unroll
        for (int r = 0; r < 8; r++) { a0[r][0]=0ull;a0[r][1]=0ull;a1[r][0]=0ull;a1[r][1]=0ull; }
        gstaged<2>(agg, 128, lW,         128, 128, stg, t, ty, txc, a0);
        gstaged<2>(agg, 128, lW + 16384, 128, 128, stg, t, ty, txc, a1);
        #pragma unroll
        for (int r = 0; r < 8; r++) {
            int row = ty * 8 + r;
            #pragma unroll
            for (int j = 0; j < 2; j++) {
                float l0, h0, l1, h1v;
                unpackf2(a0[r][j], l0, h0);
                unpackf2(a1[r][j], l1, h1v);
                int col = txc * 4 + 2 * j;
                float x0 = xs[row * 128 + col], x1 = xs[row * 128 + col + 1];
                float vlo = 0.5f * (leaky(x0 + l0) + leaky(x0 + l1));
                float vhi = 0.5f * (leaky(x1 + h0) + leaky(x1 + h1v));
                *(float2*)(axc + row * 128 + col) = make_float2(vlo, vhi);
            }
        }
    }
    __syncthreads();

    // ---- stage 5: q2 = hop2(x_c) for rank0 (rank1 keeps qt in qs) ----
    if (rank == 0) {
        float* tmp = h1b;
        unsigned long long acc[8][2];
        #pragma unroll
        for (int r = 0; r < 8; r++) { acc[r][0] = 0ull; acc[r][1] = 0ull; }
        gseg<2>(Ms, 64, axc, 128, 64, ty, txc, acc);
        estore<2, 0>(tmp, 128, ty, txc, acc);
        __syncthreads();
        unsigned long long acc2[8][2];
        #pragma unroll
        for (int r = 0; r < 8; r++) { acc2[r][0] = 0ull; acc2[r][1] = 0ull; }
        gseg<2>(Ms, 64, tmp, 128, 64, ty, txc, acc2);
        estore<2, 0>(qs, 128, ty, txc, acc2);
        __syncthreads();
    }

    // ---- stage 6: attention #2 (head = 2 + rank), kv = x_c -> gown ----
    attention(sm, t, ty, txc, axc, qs, h1b, 2 + (int)rank, Wk, W1, W2, W3, gown);

    cluster_sync();
    if (t < 64) gpeer[t] = dsread(gown + t, rank ^ 1);
    __syncthreads();

    // ---- stage 7: cluster score softmax + top-52 (duplicated per rank) ----
    if (t < 64) sscore[t] = gown[t] + gpeer[t];
    __syncthreads();
    softmax64(sscore, red, t);
    if (t < 32) {
        float v0 = sscore[t], v1 = sscore[t + 32];
        for (int j = 0; j < KK; j++) {
            float mv = v0; int mi = t;
            if (v1 > mv) { mv = v1; mi = t + 32; }
            #pragma unroll
            for (int off = 16; off; off >>= 1) {
                float ov = __shfl_xor_sync(0xffffffffu, mv, off);
                int   oi = __shfl_xor_sync(0xffffffffu, mi, off);
                if (ov > mv || (ov == mv && oi < mi)) { mv = ov; mi = oi; }
            }
            if (t == 0) permsh[j] = mi;
            if (mi < 32) { if (t == mi) v0 = -3.0e38f; }
            else         { if (t == mi - 32) v1 = -3.0e38f; }
        }
    }
    __syncthreads();

    // ---- stage 8: outputs ----
    if (rank == 0) {
        for (int i = t; i < KK * 32; i += NTHR) {
            int e = i >> 5, c4 = (i & 31) * 4;
            int p = permsh[e];
            float sc = sscore[p];
            float4 xv = *(const float4*)(xs + p * 128 + c4);
            *(float4*)(outx + (size_t)(b * KK + e) * 128 + c4) =
                make_float4(xv.x * sc, xv.y * sc, xv.z * sc, xv.w * sc);
        }
        if (t < KK) {
            int p = permsh[t];
            outb[b * KK + t] = (float)b;
            outp[b * KK + t] = (float)(b * 64 + p);
        }
    }

    // A2 block: T = A_d @ S_sel ; A2 = S_sel^T @ T (rows split by rank)
    float* T = h1b;   // 64*52 floats
    for (int i = t; i < 64 * KK; i += NTHR) {
        int r = i / KK, j = i - r * KK;
        int cj = permsh[j];
        float acc = 0.0f;
        #pragma unroll
        for (int c = 0; c < 64; c++) acc += Ms[c * 64 + r] * Ss[c * 64 + cj];
        T[i] = acc;
    }
    __syncthreads();
    for (int o = t; o < 26 * KK; o += NTHR) {
        int il = o / KK, j = o - il * KK;
        int i = (int)rank * 26 + il;
        float v;
        if (i == j) v = 1.0f;
        else {
            int ci = permsh[i];
            v = 0.0f;
            #pragma unroll
            for (int r = 0; r < 64; r++) v += Ss[r * 64 + ci] * T[r * KK + j];
        }
        outA2[(size_t)(b * KK + i) * NK + (size_t)(b * KK + j)] = v;
    }
}

// =======================================================================
extern "C" void kernel_launch(void* const* d_in, const int* in_sizes, int n_in,
                              void* d_out, int out_size) {
    const float* x   = (const float*)d_in[0];
    const int*   ei  = (const int*)d_in[1];
    const float* ewt = (const float*)d_in[2];
    const float* tx  = (const float*)d_in[3];
    const float* Wk  = (const float*)d_in[5];
    const float* W1  = (const float*)d_in[6];
    const float* W2  = (const float*)d_in[7];
    const float* W3  = (const float*)d_in[8];
    const float* lW  = (const float*)d_in[9];
    float* out = (float*)d_out;

    float* out_x    = out;
    float* out_A2   = out + (size_t)NK * HH;
    float* out_bat  = out + (size_t)NK * HH + (size_t)NK * NK;
    float* out_perm = out_bat + NK;

    cudaFuncSetAttribute(mega_k, cudaFuncAttributeMaxDynamicSharedMemorySize, SM_BYTES);

    mega_k<<<2 * BB, NTHR, SM_BYTES>>>(x, ei, ewt, tx, Wk, W1, W2, W3, lW,
                                       out_x, out_A2, out_bat, out_perm);
}

// round 8
// speedup vs baseline: 1.5205x; 1.5205x over previous
#include <cuda_runtime.h>
#include <cstdint>
#include <math.h>

#define BB   64
#define HH   128
#define NT   4096
#define EE   131072
#define KK   52
#define NK   3328
#define NEG  0.01f

// Global scratch: folded W1 (4 heads x 384 x 256):
// rows 0..127 = W1_0+W1_2, 128..255 = W1_1-W1_2, 256..383 = W1_3
__device__ float g_wf[4*384*256];

// ---------------- shared memory layout (float offsets) — 171 KB total ------
#define SM_M    0          // 4096  M[c*64+r] = A_d[r][c]
#define SM_S    4096       // 4096  S[r*64+c]
#define SM_X    8192       // 8192  x -> xc (overwritten)
#define SM_Q    16384      // 8192  q (xq / qt / xq2)
#define SM_A    24576      // 8192  hop-tmp / a / agg / A2-T
#define SM_H    32768      // 8192  h1half / h2
#define SM_MISC 40960
#define MS_DEG   0
#define MS_DINV  64
#define MS_FOWN  128
#define MS_FPEER 192
#define MS_GOWN  256
#define MS_GPEER 320
#define MS_SCORE 384
#define MS_RED   448       // 256 floats
#define MS_PERM  704       // 64 ints
#define MS_CNT   768       // 2048 ints (packed 2x uint16)
#define SM_TOTALF (SM_MISC + 768 + 2048)
#define SM_BYTES  (SM_TOTALF * 4)

#define NTHR 256

__device__ __forceinline__ float leaky(float v) { return v > 0.0f ? v : NEG * v; }

// ---- packed fp32 (f32x2) ----
__device__ __forceinline__ unsigned long long packf2(float f) {
    unsigned long long d; unsigned int u = __float_as_uint(f);
    asm("mov.b64 %0, {%1, %1};" : "=l"(d) : "r"(u));
    return d;
}
__device__ __forceinline__ void fma2(unsigned long long& acc,
                                     unsigned long long a, unsigned long long b) {
    asm("fma.rn.f32x2 %0, %1, %2, %0;" : "+l"(acc) : "l"(a), "l"(b));
}
__device__ __forceinline__ unsigned long long mul2(unsigned long long a,
                                                   unsigned long long b) {
    unsigned long long o;
    asm("mul.rn.f32x2 %0, %1, %2;" : "=l"(o) : "l"(a), "l"(b));
    return o;
}
__device__ __forceinline__ void unpackf2(unsigned long long v, float& lo, float& hi) {
    unsigned int ul, uh;
    asm("mov.b64 {%0, %1}, %2;" : "=r"(ul), "=r"(uh) : "l"(v));
    lo = __uint_as_float(ul); hi = __uint_as_float(uh);
}

// ---- cluster helpers ----
__device__ __forceinline__ void cluster_sync() {
    asm volatile("barrier.cluster.arrive.aligned;" ::: "memory");
    asm volatile("barrier.cluster.wait.aligned;" ::: "memory");
}
__device__ __forceinline__ float dsread(const float* p, unsigned peer) {
    unsigned addr = (unsigned)__cvta_generic_to_shared((void*)p);
    unsigned ra; float v;
    asm volatile("mapa.shared::cluster.u32 %0, %1, %2;" : "=r"(ra) : "r"(addr), "r"(peer));
    asm volatile("ld.shared::cluster.f32 %0, [%1];" : "=f"(v) : "r"(ra));
    return v;
}

// ---- GEMM microkernel: C[64 x N], 8 warps, thread tile 8 rows x (2*JN) cols
template<int JN>
__device__ __forceinline__ void gseg(const float* __restrict__ As, int ldA,
                                     const float* __restrict__ W, int wld, int K,
                                     int ty, int txc, unsigned long long acc[8][JN]) {
    const float* a0 = As + ty * 8 * ldA;
    const float* wbase = W + txc * (2 * JN);
    for (int k = 0; k < K; k += 4) {
        float4 av[8];
        #pragma unroll
        for (int r = 0; r < 8; r++) av[r] = *(const float4*)(a0 + r * ldA + k);
        #pragma unroll
        for (int kk = 0; kk < 4; kk++) {
            const ulonglong2 p0 = *(const ulonglong2*)(wbase + (size_t)(k + kk) * wld);
            unsigned long long b2[JN];
            b2[0] = p0.x; b2[1] = p0.y;
            if (JN == 4) {
                const ulonglong2 p1 = *(const ulonglong2*)(wbase + (size_t)(k + kk) * wld + 4);
                b2[2] = p1.x; b2[3] = p1.y;
            }
            #pragma unroll
            for (int r = 0; r < 8; r++) {
                float aval = kk == 0 ? av[r].x : kk == 1 ? av[r].y : kk == 2 ? av[r].z : av[r].w;
                unsigned long long a2 = packf2(aval);
                #pragma unroll
                for (int j = 0; j < JN; j++) fma2(acc[r][j], a2, b2[j]);
            }
        }
    }
}

// Fused h1 microkernel: acc += a@Wf0 + q@Wf1 + (a*q)@Wf2 over K=128, half cols
__device__ __forceinline__ void gsegH1(const float* __restrict__ a,
                                       const float* __restrict__ q,
                                       const float* __restrict__ Wf, int half,
                                       int ty, int txc, unsigned long long acc[8][2]) {
    const float* a0 = a + ty * 8 * 128;
    const float* q0 = q + ty * 8 * 128;
    const float* w0 = Wf + half * 128 + txc * 4;
    for (int k = 0; k < 128; k += 4) {
        float4 av[8], qv[8];
        #pragma unroll
        for (int r = 0; r < 8; r++) { av[r] = *(const float4*)(a0 + r * 128 + k);
                                      qv[r] = *(const float4*)(q0 + r * 128 + k); }
        #pragma unroll
        for (int kk = 0; kk < 4; kk++) {
            const ulonglong2 wa = *(const ulonglong2*)(w0 + (size_t)(k + kk) * 256);
            const ulonglong2 wq = *(const ulonglong2*)(w0 + (size_t)(128 + k + kk) * 256);
            const ulonglong2 wm = *(const ulonglong2*)(w0 + (size_t)(256 + k + kk) * 256);
            #pragma unroll
            for (int r = 0; r < 8; r++) {
                float aval = kk == 0 ? av[r].x : kk == 1 ? av[r].y : kk == 2 ? av[r].z : av[r].w;
                float qval = kk == 0 ? qv[r].x : kk == 1 ? qv[r].y : kk == 2 ? qv[r].z : qv[r].w;
                unsigned long long a2 = packf2(aval);
                unsigned long long q2 = packf2(qval);
                unsigned long long m2 = mul2(a2, q2);
                fma2(acc[r][0], a2, wa.x); fma2(acc[r][1], a2, wa.y);
                fma2(acc[r][0], q2, wq.x); fma2(acc[r][1], q2, wq.y);
                fma2(acc[r][0], m2, wm.x); fma2(acc[r][1], m2, wm.y);
            }
        }
    }
}

// Transposed-A variant for agg: A[c][k] = S[k*64+c]
template<int JN>
__device__ __forceinline__ void gsegT(const float* __restrict__ S,
                                      const float* __restrict__ W, int wld, int K,
                                      int ty, int txc, unsigned long long acc[8][JN]) {
    int c0 = ty * 8;
    const float* wbase = W + txc * (2 * JN);
    for (int k = 0; k < K; k++) {
        const ulonglong2 p0 = *(const ulonglong2*)(wbase + (size_t)k * wld);
        unsigned long long b2[2] = { p0.x, p0.y };
        #pragma unroll
        for (int r = 0; r < 8; r++) {
            unsigned long long a2 = packf2(S[k * 64 + c0 + r]);
            #pragma unroll
            for (int j = 0; j < JN; j++) fma2(acc[r][j], a2, b2[j]);
        }
    }
}

template<int JN, int ACT>
__device__ __forceinline__ void estore(float* C, int ldC, int ty, int txc,
                                       unsigned long long acc[8][JN]) {
    #pragma unroll
    for (int r = 0; r < 8; r++) {
        float* crow = C + (ty * 8 + r) * ldC + txc * (2 * JN);
        #pragma unroll
        for (int j = 0; j < JN; j++) {
            float lo, hi; unpackf2(acc[r][j], lo, hi);
            if (ACT == 1) { lo = leaky(lo); hi = leaky(hi); }
            ((float2*)crow)[j] = make_float2(lo, hi);
        }
    }
}

// ---- in-place softmax over v[0..63] ----
__device__ void softmax64(float* v, float* red, int t) {
    if (t < 64) red[t] = v[t];
    __syncthreads();
    for (int o = 32; o; o >>= 1) { if (t < o) red[t] = fmaxf(red[t], red[t + o]); __syncthreads(); }
    float m = red[0];
    __syncthreads();
    if (t < 64) { float e = expf(v[t] - m); v[t] = e; red[t] = e; }
    __syncthreads();
    for (int o = 32; o; o >>= 1) { if (t < o) red[t] += red[t + o]; __syncthreads(); }
    float d = red[0];
    __syncthreads();
    if (t < 64) v[t] = v[t] / d;
    __syncthreads();
}

// ---- attention branch: fout = segsoftmax(leaky(MLP(kv, q))) ---------------
// uses slots A (a) and H (h1half / h2); q in Q slot (read-only here)
__device__ void attention(float* sm, int t, int ty, int txc,
                          const float* kv, const float* q,
                          int head, const float* Wk, const float* W2,
                          const float* W3, float* fout) {
    float* red = sm + SM_MISC + MS_RED;
    float* Ab  = sm + SM_A;
    float* Hb  = sm + SM_H;

    // a = kv @ Wk[head]
    {
        unsigned long long acc[8][2];
        #pragma unroll
        for (int r = 0; r < 8; r++) { acc[r][0] = 0ull; acc[r][1] = 0ull; }
        gseg<2>(kv, 128, Wk + head * 16384, 128, 128, ty, txc, acc);
        estore<2, 0>(Ab, 128, ty, txc, acc);
    }
    __syncthreads();

    // h2 accumulated across two h1 halves
    unsigned long long h2acc[8][2];
    #pragma unroll
    for (int r = 0; r < 8; r++) { h2acc[r][0] = 0ull; h2acc[r][1] = 0ull; }
    const float* Wf = g_wf + (size_t)head * 384 * 256;
    #pragma unroll
    for (int half = 0; half < 2; half++) {
        unsigned long long acc[8][2];
        #pragma unroll
        for (int r = 0; r < 8; r++) { acc[r][0] = 0ull; acc[r][1] = 0ull; }
        gsegH1(Ab, q, Wf, half, ty, txc, acc);
        estore<2, 1>(Hb, 128, ty, txc, acc);   // h1half (leaky)
        __syncthreads();
        gseg<2>(Hb, 128, W2 + head * 32768 + half * 16384, 128, 128, ty, txc, h2acc);
        __syncthreads();                        // protect Hb before next overwrite
    }
    estore<2, 1>(Hb, 128, ty, txc, h2acc);      // h2 (leaky)
    __syncthreads();

    // logit = leaky(h2 @ W3[head]); segment softmax over 64
    {
        int row = t >> 2, part = t & 3;
        const float4* hp = (const float4*)(Hb + row * 128 + part * 32);
        const float4* wp = (const float4*)(W3 + head * 128 + part * 32);
        float s = 0.0f;
        #pragma unroll
        for (int i = 0; i < 8; i++) {
            float4 a = hp[i], b = wp[i];
            s += a.x * b.x + a.y * b.y + a.z * b.z + a.w * b.w;
        }
        red[t] = s;
    }
    __syncthreads();
    if (t < 64) fout[t] = leaky(red[t * 4] + red[t * 4 + 1] + red[t * 4 + 2] + red[t * 4 + 3]);
    __syncthreads();
    softmax64(fout, red, t);
}

// ---------------- fold W1 ----------------
__global__ void fold_k(const float* __restrict__ W1) {
    int i = blockIdx.x * 256 + threadIdx.x;
    if (i >= 4 * 384 * 256) return;
    int w = i / (384 * 256);
    int rem = i - w * (384 * 256);
    int r = rem >> 8, c = rem & 255;
    const float* base = W1 + (size_t)w * 512 * 256;
    float v;
    if (r < 128)      v = base[r * 256 + c] + base[(r + 256) * 256 + c];
    else if (r < 256) v = base[r * 256 + c] - base[(r + 128) * 256 + c];
    else              v = base[(r + 128) * 256 + c];
    g_wf[i] = v;
}

// ---------------- THE mega kernel: one 2-CTA cluster = one batch -----------
extern __shared__ float sm[];

__global__ void __launch_bounds__(NTHR, 1) __cluster_dims__(2, 1, 1)
mega_k(const float* __restrict__ xg, const int* __restrict__ ei,
       const float* __restrict__ ew, const float* __restrict__ tx,
       const float* __restrict__ Wk, const float* __restrict__ W2,
       const float* __restrict__ W3, const float* __restrict__ lW,
       float* __restrict__ outx, float* __restrict__ outA2,
       float* __restrict__ outb, float* __restrict__ outp) {
    int t = threadIdx.x;
    int ty = t >> 5, txc = t & 31;
    int b = blockIdx.x >> 1;
    unsigned rank = blockIdx.x & 1;

    float* Ms    = sm + SM_M;
    float* Ss    = sm + SM_S;
    float* xs    = sm + SM_X;       // x, later xc
    float* qs    = sm + SM_Q;
    float* Ab    = sm + SM_A;
    float* Hb    = sm + SM_H;
    float* degs  = sm + SM_MISC + MS_DEG;
    float* dinvs = sm + SM_MISC + MS_DINV;
    float* fown  = sm + SM_MISC + MS_FOWN;
    float* fpeer = sm + SM_MISC + MS_FPEER;
    float* gown  = sm + SM_MISC + MS_GOWN;
    float* gpeer = sm + SM_MISC + MS_GPEER;
    float* sscore= sm + SM_MISC + MS_SCORE;
    float* red   = sm + SM_MISC + MS_RED;
    int*   permsh= (int*)(sm + SM_MISC + MS_PERM);
    int*   cw    = (int*)(sm + SM_MISC + MS_CNT);

    // ---- zero this CTA's A2 row-strip (26 rows x NK), overlapped ----
    {
        float4 z = make_float4(0.0f, 0.0f, 0.0f, 0.0f);
        float4* dst = (float4*)(outA2 + ((size_t)b * KK + rank * 26) * NK);
        for (int i = t; i < 26 * NK / 4; i += NTHR) dst[i] = z;
    }

    // ---- stage 0: load x, init, build deg/dinv/M/Cnt ----
    for (int i = t; i < 4096; i += NTHR) Ms[i] = 0.0f;
    for (int i = t; i < 2048; i += NTHR) cw[i] = 0;
    if (t < 64) degs[t] = 1.0f;
    for (int i = t * 4; i < 8192; i += NTHR * 4)
        *(float4*)(xs + i) = *(const float4*)(xg + (size_t)b * 8192 + i);
    __syncthreads();

    int er[8], ec[8]; float ewv[8];
    #pragma unroll
    for (int u = 0; u < 8; u++) {
        int e = b * 2048 + t + u * NTHR;
        er[u] = ei[e] - b * 64;
        ec[u] = ei[EE + e] - b * 64;
        ewv[u] = ew[e];
        atomicAdd(&degs[ec[u]], ewv[u]);
    }
    __syncthreads();
    if (t < 64) {
        float d = degs[t];
        dinvs[t] = d > 0.0f ? (1.0f / sqrtf(fmaxf(d, 1e-12f))) : 0.0f;
    }
    __syncthreads();
    #pragma unroll
    for (int u = 0; u < 8; u++) {
        atomicAdd(&Ms[ec[u] * 64 + er[u]], dinvs[er[u]] * ewv[u] * dinvs[ec[u]]);
        atomicAdd(&cw[(er[u] * 64 + ec[u]) >> 1], 1 << ((ec[u] & 1) * 16));
    }
    if (t < 64) {
        float dv = dinvs[t];
        atomicAdd(&Ms[t * 64 + t], dv * dv);
        atomicAdd(&cw[(t * 64 + t) >> 1], 1 << ((t & 1) * 16));
    }
    __syncthreads();

    // ---- stage 1: q = hop2(x) for rank0; q = broadcast target for rank1 ----
    if (rank == 0) {
        unsigned long long acc[8][2];
        #pragma unroll
        for (int r = 0; r < 8; r++) { acc[r][0] = 0ull; acc[r][1] = 0ull; }
        gseg<2>(Ms, 64, xs, 128, 64, ty, txc, acc);
        estore<2, 0>(Ab, 128, ty, txc, acc);
        __syncthreads();
        unsigned long long acc2[8][2];
        #pragma unroll
        for (int r = 0; r < 8; r++) { acc2[r][0] = 0ull; acc2[r][1] = 0ull; }
        gseg<2>(Ms, 64, Ab, 128, 64, ty, txc, acc2);
        estore<2, 0>(qs, 128, ty, txc, acc2);
    } else {
        for (int i = t * 4; i < 8192; i += NTHR * 4)
            *(float4*)(qs + i) = *(const float4*)(tx + b * 128 + (i & 127));
    }
    __syncthreads();

    // ---- stage 2: attention #1 (head = rank) -> fown ----
    attention(sm, t, ty, txc, xs, qs, (int)rank, Wk, W2, W3, fown);

    cluster_sync();
    if (t < 64) fpeer[t] = dsread(fown + t, rank ^ 1);
    __syncthreads();

    // ---- stage 3: build S (edge softmax, count-weighted) ----
    {
        const float* f1 = rank ? fpeer : fown;
        const float* f2 = rank ? fown : fpeer;
        int c = t >> 2, rq = t & 3;
        float f1c = f1[c];
        float mx = -3.0e38f;
        for (int r = rq * 16; r < rq * 16 + 16; r++) {
            int cnt = (cw[(r * 64 + c) >> 1] >> ((c & 1) * 16)) & 0xffff;
            if (cnt) mx = fmaxf(mx, leaky(f1c + f2[r]));
        }
        red[t] = mx; __syncthreads();
        mx = fmaxf(fmaxf(red[c * 4], red[c * 4 + 1]), fmaxf(red[c * 4 + 2], red[c * 4 + 3]));
        __syncthreads();
        float dp = 0.0f;
        for (int r = rq * 16; r < rq * 16 + 16; r++) {
            int cnt = (cw[(r * 64 + c) >> 1] >> ((c & 1) * 16)) & 0xffff;
            float e = 0.0f;
            if (cnt) e = (float)cnt * expf(leaky(f1c + f2[r]) - mx);
            Ss[r * 64 + c] = e; dp += e;
        }
        red[t] = dp; __syncthreads();
        float inv = 1.0f / (red[c * 4] + red[c * 4 + 1] + red[c * 4 + 2] + red[c * 4 + 3]);
        for (int r = rq * 16; r < rq * 16 + 16; r++) Ss[r * 64 + c] *= inv;
        __syncthreads();
    }

    // ---- stage 4: agg = S^T x -> Ab ; xc = mean_h leaky(x + agg @ lW[h]) ----
    {
        unsigned long long acc[8][2];
        #pragma unroll
        for (int r = 0; r < 8; r++) { acc[r][0] = 0ull; acc[r][1] = 0ull; }
        gsegT<2>(Ss, xs, 128, 64, ty, txc, acc);
        estore<2, 0>(Ab, 128, ty, txc, acc);
    }
    __syncthreads();
    {
        unsigned long long a0[8][2], a1[8][2];
        #pragma unroll
        for (int r = 0; r < 8; r++) { a0[r][0]=0ull;a0[r][1]=0ull;a1[r][0]=0ull;a1[r][1]=0ull; }
        gseg<2>(Ab, 128, lW,         128, 128, ty, txc, a0);
        gseg<2>(Ab, 128, lW + 16384, 128, 128, ty, txc, a1);
        #pragma unroll
        for (int r = 0; r < 8; r++) {
            int row = ty * 8 + r;
            #pragma unroll
            for (int j = 0; j < 2; j++) {
                float l0, h0, l1, h1v;
                unpackf2(a0[r][j], l0, h0);
                unpackf2(a1[r][j], l1, h1v);
                int col = txc * 4 + 2 * j;
                float x0 = xs[row * 128 + col], x1 = xs[row * 128 + col + 1];
                float vlo = 0.5f * (leaky(x0 + l0) + leaky(x0 + l1));
                float vhi = 0.5f * (leaky(x1 + h0) + leaky(x1 + h1v));
                *(float2*)(xs + row * 128 + col) = make_float2(vlo, vhi);  // x -> xc in place
            }
        }
    }
    __syncthreads();

    // ---- stage 5: q2 = hop2(xc) for rank0 (rank1 keeps qt in qs) ----
    if (rank == 0) {
        unsigned long long acc[8][2];
        #pragma unroll
        for (int r = 0; r < 8; r++) { acc[r][0] = 0ull; acc[r][1] = 0ull; }
        gseg<2>(Ms, 64, xs, 128, 64, ty, txc, acc);
        estore<2, 0>(Ab, 128, ty, txc, acc);
        __syncthreads();
        unsigned long long acc2[8][2];
        #pragma unroll
        for (int r = 0; r < 8; r++) { acc2[r][0] = 0ull; acc2[r][1] = 0ull; }
        gseg<2>(Ms, 64, Ab, 128, 64, ty, txc, acc2);
        estore<2, 0>(qs, 128, ty, txc, acc2);
        __syncthreads();
    }

    // ---- stage 6: attention #2 (head = 2 + rank), kv = xc -> gown ----
    attention(sm, t, ty, txc, xs, qs, 2 + (int)rank, Wk, W2, W3, gown);

    cluster_sync();
    if (t < 64) gpeer[t] = dsread(gown + t, rank ^ 1);
    __syncthreads();

    // ---- stage 7: cluster score softmax + top-52 ----
    if (t < 64) sscore[t] = gown[t] + gpeer[t];
    __syncthreads();
    softmax64(sscore, red, t);
    if (t < 32) {
        float v0 = sscore[t], v1 = sscore[t + 32];
        for (int j = 0; j < KK; j++) {
            float mv = v0; int mi = t;
            if (v1 > mv) { mv = v1; mi = t + 32; }
            #pragma unroll
            for (int off = 16; off; off >>= 1) {
                float ov = __shfl_xor_sync(0xffffffffu, mv, off);
                int   oi = __shfl_xor_sync(0xffffffffu, mi, off);
                if (ov > mv || (ov == mv && oi < mi)) { mv = ov; mi = oi; }
            }
            if (t == 0) permsh[j] = mi;
            if (mi < 32) { if (t == mi) v0 = -3.0e38f; }
            else         { if (t == mi - 32) v1 = -3.0e38f; }
        }
    }
    __syncthreads();

    // ---- stage 8: outputs ----
    if (rank == 0) {
        // x_out: re-read x from global (xs now holds xc)
        for (int i = t; i < KK * 32; i += NTHR) {
            int e = i >> 5, c4 = (i & 31) * 4;
            int p = permsh[e];
            float sc = sscore[p];
            float4 xv = *(const float4*)(xg + (size_t)b * 8192 + p * 128 + c4);
            *(float4*)(outx + (size_t)(b * KK + e) * 128 + c4) =
                make_float4(xv.x * sc, xv.y * sc, xv.z * sc, xv.w * sc);
        }
        if (t < KK) {
            int p = permsh[t];
            outb[b * KK + t] = (float)b;
            outp[b * KK + t] = (float)(b * 64 + p);
        }
    }

    // A2 block: T = A_d @ S_sel (in Ab); A2 rows split by rank
    float* T = Ab;   // 64*52 floats
    __syncthreads();
    for (int i = t; i < 64 * KK; i += NTHR) {
        int r = i / KK, j = i - r * KK;
        int cj = permsh[j];
        float acc = 0.0f;
        #pragma unroll
        for (int c = 0; c < 64; c++) acc += Ms[c * 64 + r] * Ss[c * 64 + cj];
        T[i] = acc;
    }
    __syncthreads();
    for (int o = t; o < 26 * KK; o += NTHR) {
        int il = o / KK, j = o - il * KK;
        int i = (int)rank * 26 + il;
        float v;
        if (i == j) v = 1.0f;
        else {
            int ci = permsh[i];
            v = 0.0f;
            #pragma unroll
            for (int r = 0; r < 64; r++) v += Ss[r * 64 + ci] * T[r * KK + j];
        }
        outA2[(size_t)(b * KK + i) * NK + (size_t)(b * KK + j)] = v;
    }
}

// =======================================================================
extern "C" void kernel_launch(void* const* d_in, const int* in_sizes, int n_in,
                              void* d_out, int out_size) {
    const float* x   = (const float*)d_in[0];
    const int*   ei  = (const int*)d_in[1];
    const float* ewt = (const float*)d_in[2];
    const float* tx  = (const float*)d_in[3];
    const float* Wk  = (const float*)d_in[5];
    const float* W1  = (const float*)d_in[6];
    const float* W2  = (const float*)d_in[7];
    const float* W3  = (const float*)d_in[8];
    const float* lW  = (const float*)d_in[9];
    float* out = (float*)d_out;

    float* out_x    = out;
    float* out_A2   = out + (size_t)NK * HH;
    float* out_bat  = out + (size_t)NK * HH + (size_t)NK * NK;
    float* out_perm = out_bat + NK;

    cudaFuncSetAttribute(mega_k, cudaFuncAttributeMaxDynamicSharedMemorySize, SM_BYTES);

    fold_k<<<(4 * 384 * 256 + 255) / 256, 256>>>(W1);
    mega_k<<<2 * BB, NTHR, SM_BYTES>>>(x, ei, ewt, tx, Wk, W2, W3, lW,
                                       out_x, out_A2, out_bat, out_perm);
}

// round 10
// speedup vs baseline: 1.7289x; 1.1370x over previous
#include <cuda_runtime.h>
#include <cstdint>
#include <math.h>

#define BB   64
#define HH   128
#define NT   4096
#define EE   131072
#define KK   52
#define NK   3328
#define NEG  0.01f

// Global scratch: folded W1 (4 heads x 384 x 256):
// rows 0..127 = W1_0+W1_2, 128..255 = W1_1-W1_2, 256..383 = W1_3
__device__ float g_wf[4*384*256];

// ---------------- shared memory layout (float offsets) — 171 KB total ------
#define SM_M    0          // 4096  M[c*64+r] = A_d[r][c]
#define SM_S    4096       // 4096  S[r*64+c]
#define SM_X    8192       // 8192  x -> xc (overwritten)
#define SM_Q    16384      // 8192  q (xq / qt / xq2)
#define SM_A    24576      // 8192  hop-tmp / a / agg / A2-T
#define SM_H    32768      // 8192  h1half / h2
#define SM_MISC 40960
#define MS_DEG   0
#define MS_DINV  64
#define MS_FOWN  128
#define MS_FPEER 192
#define MS_GOWN  256
#define MS_GPEER 320
#define MS_SCORE 384
#define MS_RED   448       // 256 floats
#define MS_PERM  704       // 64 ints
#define MS_CNT   768       // 2048 ints (packed 2x uint16)
#define SM_TOTALF (SM_MISC + 768 + 2048)
#define SM_BYTES  (SM_TOTALF * 4)

#define NTHR 256

__device__ __forceinline__ float leaky(float v) { return v > 0.0f ? v : NEG * v; }

// ---- packed fp32 (f32x2) ----
__device__ __forceinline__ unsigned long long packf2(float f) {
    unsigned long long d; unsigned int u = __float_as_uint(f);
    asm("mov.b64 %0, {%1, %1};" : "=l"(d) : "r"(u));
    return d;
}
__device__ __forceinline__ void fma2(unsigned long long& acc,
                                     unsigned long long a, unsigned long long b) {
    asm("fma.rn.f32x2 %0, %1, %2, %0;" : "+l"(acc) : "l"(a), "l"(b));
}
__device__ __forceinline__ unsigned long long mul2(unsigned long long a,
                                                   unsigned long long b) {
    unsigned long long o;
    asm("mul.rn.f32x2 %0, %1, %2;" : "=l"(o) : "l"(a), "l"(b));
    return o;
}
__device__ __forceinline__ void unpackf2(unsigned long long v, float& lo, float& hi) {
    unsigned int ul, uh;
    asm("mov.b64 {%0, %1}, %2;" : "=r"(ul), "=r"(uh) : "l"(v));
    lo = __uint_as_float(ul); hi = __uint_as_float(uh);
}

// ---- cluster helpers ----
__device__ __forceinline__ void cluster_sync() {
    asm volatile("barrier.cluster.arrive.aligned;" ::: "memory");
    asm volatile("barrier.cluster.wait.aligned;" ::: "memory");
}
__device__ __forceinline__ float dsread(const float* p, unsigned peer) {
    unsigned addr = (unsigned)__cvta_generic_to_shared((void*)p);
    unsigned ra; float v;
    asm volatile("mapa.shared::cluster.u32 %0, %1, %2;" : "=r"(ra) : "r"(addr), "r"(peer));
    asm volatile("ld.shared::cluster.f32 %0, [%1];" : "=f"(v) : "r"(ra));
    return v;
}

// ---- GEMM microkernel: C[64 x 128], 8 warps, tile 8 rows x 4 cols (f32x2) --
// Compile-time K; W prefetched one 4-k chunk ahead in registers (hides L2).
template<int K>
__device__ __forceinline__ void gseg(const float* __restrict__ As, int ldA,
                                     const float* __restrict__ W, int wld,
                                     int ty, int txc, unsigned long long acc[8][2]) {
    const float* a0 = As + ty * 8 * ldA;
    const float* wbase = W + txc * 4;
    ulonglong2 wc[4], wn[4];
    #pragma unroll
    for (int kk = 0; kk < 4; kk++)
        wc[kk] = *(const ulonglong2*)(wbase + (size_t)kk * wld);
    #pragma unroll 2
    for (int k = 0; k < K; k += 4) {
        if (k + 4 < K) {
            #pragma unroll
            for (int kk = 0; kk < 4; kk++)
                wn[kk] = *(const ulonglong2*)(wbase + (size_t)(k + 4 + kk) * wld);
        }
        float4 av[8];
        #pragma unroll
        for (int r = 0; r < 8; r++) av[r] = *(const float4*)(a0 + r * ldA + k);
        #pragma unroll
        for (int kk = 0; kk < 4; kk++) {
            unsigned long long b0 = wc[kk].x, b1 = wc[kk].y;
            #pragma unroll
            for (int r = 0; r < 8; r++) {
                float aval = kk == 0 ? av[r].x : kk == 1 ? av[r].y : kk == 2 ? av[r].z : av[r].w;
                unsigned long long a2 = packf2(aval);
                fma2(acc[r][0], a2, b0);
                fma2(acc[r][1], a2, b1);
            }
        }
        #pragma unroll
        for (int kk = 0; kk < 4; kk++) wc[kk] = wn[kk];
    }
}

// Fused h1 microkernel: acc += a@Wf0 + q@Wf1 + (a*q)@Wf2, K=128, half cols.
// 2-k chunks; all 3 weight streams prefetched one chunk ahead.
__device__ __forceinline__ void gsegH1(const float* __restrict__ a,
                                       const float* __restrict__ q,
                                       const float* __restrict__ Wf, int half,
                                       int ty, int txc, unsigned long long acc[8][2]) {
    const float* a0 = a + ty * 8 * 128;
    const float* q0 = q + ty * 8 * 128;
    const float* w0 = Wf + half * 128 + txc * 4;
    ulonglong2 wa[2], wq[2], wm[2], na[2], nq[2], nm[2];
    #pragma unroll
    for (int kk = 0; kk < 2; kk++) {
        wa[kk] = *(const ulonglong2*)(w0 + (size_t)kk * 256);
        wq[kk] = *(const ulonglong2*)(w0 + (size_t)(128 + kk) * 256);
        wm[kk] = *(const ulonglong2*)(w0 + (size_t)(256 + kk) * 256);
    }
    #pragma unroll 2
    for (int k = 0; k < 128; k += 2) {
        if (k + 2 < 128) {
            #pragma unroll
            for (int kk = 0; kk < 2; kk++) {
                na[kk] = *(const ulonglong2*)(w0 + (size_t)(k + 2 + kk) * 256);
                nq[kk] = *(const ulonglong2*)(w0 + (size_t)(128 + k + 2 + kk) * 256);
                nm[kk] = *(const ulonglong2*)(w0 + (size_t)(256 + k + 2 + kk) * 256);
            }
        }
        float2 av[8], qv[8];
        #pragma unroll
        for (int r = 0; r < 8; r++) {
            av[r] = *(const float2*)(a0 + r * 128 + k);
            qv[r] = *(const float2*)(q0 + r * 128 + k);
        }
        #pragma unroll
        for (int kk = 0; kk < 2; kk++) {
            #pragma unroll
            for (int r = 0; r < 8; r++) {
                float aval = kk ? av[r].y : av[r].x;
                float qval = kk ? qv[r].y : qv[r].x;
                unsigned long long a2 = packf2(aval);
                unsigned long long q2 = packf2(qval);
                unsigned long long m2 = mul2(a2, q2);
                fma2(acc[r][0], a2, wa[kk].x); fma2(acc[r][1], a2, wa[kk].y);
                fma2(acc[r][0], q2, wq[kk].x); fma2(acc[r][1], q2, wq[kk].y);
                fma2(acc[r][0], m2, wm[kk].x); fma2(acc[r][1], m2, wm[kk].y);
            }
        }
        #pragma unroll
        for (int kk = 0; kk < 2; kk++) { wa[kk] = na[kk]; wq[kk] = nq[kk]; wm[kk] = nm[kk]; }
    }
}

// Transposed-A variant for agg: A[c][k] = S[k*64+c]
__device__ __forceinline__ void gsegT(const float* __restrict__ S,
                                      const float* __restrict__ W, int wld, int K,
                                      int ty, int txc, unsigned long long acc[8][2]) {
    int c0 = ty * 8;
    const float* wbase = W + txc * 4;
    for (int k = 0; k < K; k++) {
        const ulonglong2 p0 = *(const ulonglong2*)(wbase + (size_t)k * wld);
        #pragma unroll
        for (int r = 0; r < 8; r++) {
            unsigned long long a2 = packf2(S[k * 64 + c0 + r]);
            fma2(acc[r][0], a2, p0.x);
            fma2(acc[r][1], a2, p0.y);
        }
    }
}

template<int ACT>
__device__ __forceinline__ void estore(float* C, int ldC, int ty, int txc,
                                       unsigned long long acc[8][2]) {
    #pragma unroll
    for (int r = 0; r < 8; r++) {
        float* crow = C + (ty * 8 + r) * ldC + txc * 4;
        #pragma unroll
        for (int j = 0; j < 2; j++) {
            float lo, hi; unpackf2(acc[r][j], lo, hi);
            if (ACT == 1) { lo = leaky(lo); hi = leaky(hi); }
            ((float2*)crow)[j] = make_float2(lo, hi);
        }
    }
}

// ---- in-place softmax over v[0..63] ----
__device__ void softmax64(float* v, float* red, int t) {
    if (t < 64) red[t] = v[t];
    __syncthreads();
    for (int o = 32; o; o >>= 1) { if (t < o) red[t] = fmaxf(red[t], red[t + o]); __syncthreads(); }
    float m = red[0];
    __syncthreads();
    if (t < 64) { float e = expf(v[t] - m); v[t] = e; red[t] = e; }
    __syncthreads();
    for (int o = 32; o; o >>= 1) { if (t < o) red[t] += red[t + o]; __syncthreads(); }
    float d = red[0];
    __syncthreads();
    if (t < 64) v[t] = v[t] / d;
    __syncthreads();
}

// ---- attention branch: fout = segsoftmax(leaky(MLP(kv, q))) ---------------
__device__ void attention(float* sm, int t, int ty, int txc,
                          const float* kv, const float* q,
                          int head, const float* Wk, const float* W2,
                          const float* W3, float* fout) {
    float* red = sm + SM_MISC + MS_RED;
    float* Ab  = sm + SM_A;
    float* Hb  = sm + SM_H;

    // a = kv @ Wk[head]
    {
        unsigned long long acc[8][2];
        #pragma unroll
        for (int r = 0; r < 8; r++) { acc[r][0] = 0ull; acc[r][1] = 0ull; }
        gseg<128>(kv, 128, Wk + head * 16384, 128, ty, txc, acc);
        estore<0>(Ab, 128, ty, txc, acc);
    }
    __syncthreads();

    // h2 accumulated across two h1 halves
    unsigned long long h2acc[8][2];
    #pragma unroll
    for (int r = 0; r < 8; r++) { h2acc[r][0] = 0ull; h2acc[r][1] = 0ull; }
    const float* Wf = g_wf + (size_t)head * 384 * 256;
    #pragma unroll 1
    for (int half = 0; half < 2; half++) {
        unsigned long long acc[8][2];
        #pragma unroll
        for (int r = 0; r < 8; r++) { acc[r][0] = 0ull; acc[r][1] = 0ull; }
        gsegH1(Ab, q, Wf, half, ty, txc, acc);
        estore<1>(Hb, 128, ty, txc, acc);   // h1half (leaky)
        __syncthreads();
        gseg<128>(Hb, 128, W2 + head * 32768 + half * 16384, 128, ty, txc, h2acc);
        __syncthreads();                     // protect Hb before next overwrite
    }
    estore<1>(Hb, 128, ty, txc, h2acc);      // h2 (leaky)
    __syncthreads();

    // logit = leaky(h2 @ W3[head]); segment softmax over 64
    {
        int row = t >> 2, part = t & 3;
        const float4* hp = (const float4*)(Hb + row * 128 + part * 32);
        const float4* wp = (const float4*)(W3 + head * 128 + part * 32);
        float s = 0.0f;
        #pragma unroll
        for (int i = 0; i < 8; i++) {
            float4 a = hp[i], b = wp[i];
            s += a.x * b.x + a.y * b.y + a.z * b.z + a.w * b.w;
        }
        red[t] = s;
    }
    __syncthreads();
    if (t < 64) fout[t] = leaky(red[t * 4] + red[t * 4 + 1] + red[t * 4 + 2] + red[t * 4 + 3]);
    __syncthreads();
    softmax64(fout, red, t);
}

// ---------------- fold W1 ----------------
__global__ void fold_k(const float* __restrict__ W1) {
    int i = blockIdx.x * 256 + threadIdx.x;
    if (i >= 4 * 384 * 256) return;
    int w = i / (384 * 256);
    int rem = i - w * (384 * 256);
    int r = rem >> 8, c = rem & 255;
    const float* base = W1 + (size_t)w * 512 * 256;
    float v;
    if (r < 128)      v = base[r * 256 + c] + base[(r + 256) * 256 + c];
    else if (r < 256) v = base[r * 256 + c] - base[(r + 128) * 256 + c];
    else              v = base[(r + 128) * 256 + c];
    g_wf[i] = v;
}

// ---------------- THE mega kernel: one 2-CTA cluster = one batch -----------
extern __shared__ float sm[];

__global__ void __launch_bounds__(NTHR, 1) __cluster_dims__(2, 1, 1)
mega_k(const float* __restrict__ xg, const int* __restrict__ ei,
       const float* __restrict__ ew, const float* __restrict__ tx,
       const float* __restrict__ Wk, const float* __restrict__ W2,
       const float* __restrict__ W3, const float* __restrict__ lW,
       float* __restrict__ outx, float* __restrict__ outA2,
       float* __restrict__ outb, float* __restrict__ outp) {
    int t = threadIdx.x;
    int ty = t >> 5, txc = t & 31;
    int b = blockIdx.x >> 1;
    unsigned rank = blockIdx.x & 1;

    float* Ms    = sm + SM_M;
    float* Ss    = sm + SM_S;
    float* xs    = sm + SM_X;       // x, later xc
    float* qs    = sm + SM_Q;
    float* Ab    = sm + SM_A;
    float* degs  = sm + SM_MISC + MS_DEG;
    float* dinvs = sm + SM_MISC + MS_DINV;
    float* fown  = sm + SM_MISC + MS_FOWN;
    float* fpeer = sm + SM_MISC + MS_FPEER;
    float* gown  = sm + SM_MISC + MS_GOWN;
    float* gpeer = sm + SM_MISC + MS_GPEER;
    float* sscore= sm + SM_MISC + MS_SCORE;
    float* red   = sm + SM_MISC + MS_RED;
    int*   permsh= (int*)(sm + SM_MISC + MS_PERM);
    int*   cw    = (int*)(sm + SM_MISC + MS_CNT);

    // ---- zero this CTA's A2 row-strip (26 rows x NK), overlapped ----
    {
        float4 z = make_float4(0.0f, 0.0f, 0.0f, 0.0f);
        float4* dst = (float4*)(outA2 + ((size_t)b * KK + rank * 26) * NK);
        for (int i = t; i < 26 * NK / 4; i += NTHR) dst[i] = z;
    }

    // ---- stage 0: load x, init, build deg/dinv/M/Cnt ----
    for (int i = t; i < 4096; i += NTHR) Ms[i] = 0.0f;
    for (int i = t; i < 2048; i += NTHR) cw[i] = 0;
    if (t < 64) degs[t] = 1.0f;
    for (int i = t * 4; i < 8192; i += NTHR * 4)
        *(float4*)(xs + i) = *(const float4*)(xg + (size_t)b * 8192 + i);
    __syncthreads();

    int er[8], ec[8]; float ewv[8];
    #pragma unroll
    for (int u = 0; u < 8; u++) {
        int e = b * 2048 + t + u * NTHR;
        er[u] = ei[e] - b * 64;
        ec[u] = ei[EE + e] - b * 64;
        ewv[u] = ew[e];
        atomicAdd(&degs[ec[u]], ewv[u]);
    }
    __syncthreads();
    if (t < 64) {
        float d = degs[t];
        dinvs[t] = d > 0.0f ? (1.0f / sqrtf(fmaxf(d, 1e-12f))) : 0.0f;
    }
    __syncthreads();
    #pragma unroll
    for (int u = 0; u < 8; u++) {
        atomicAdd(&Ms[ec[u] * 64 + er[u]], dinvs[er[u]] * ewv[u] * dinvs[ec[u]]);
        atomicAdd(&cw[(er[u] * 64 + ec[u]) >> 1], 1 << ((ec[u] & 1) * 16));
    }
    if (t < 64) {
        float dv = dinvs[t];
        atomicAdd(&Ms[t * 64 + t], dv * dv);
        atomicAdd(&cw[(t * 64 + t) >> 1], 1 << ((t & 1) * 16));
    }
    __syncthreads();

    // ---- stage 1: q = hop2(x) for rank0; q = broadcast target for rank1 ----
    if (rank == 0) {
        unsigned long long acc[8][2];
        #pragma unroll
        for (int r = 0; r < 8; r++) { acc[r][0] = 0ull; acc[r][1] = 0ull; }
        gseg<64>(Ms, 64, xs, 128, ty, txc, acc);
        estore<0>(Ab, 128, ty, txc, acc);
        __syncthreads();
        unsigned long long acc2[8][2];
        #pragma unroll
        for (int r = 0; r < 8; r++) { acc2[r][0] = 0ull; acc2[r][1] = 0ull; }
        gseg<64>(Ms, 64, Ab, 128, ty, txc, acc2);
        estore<0>(qs, 128, ty, txc, acc2);
    } else {
        for (int i = t * 4; i < 8192; i += NTHR * 4)
            *(float4*)(qs + i) = *(const float4*)(tx + b * 128 + (i & 127));
    }
    __syncthreads();

    // ---- stage 2: attention #1 (head = rank) -> fown ----
    attention(sm, t, ty, txc, xs, qs, (int)rank, Wk, W2, W3, fown);

    cluster_sync();
    if (t < 64) fpeer[t] = dsread(fown + t, rank ^ 1);
    __syncthreads();

    // ---- stage 3: build S (edge softmax, count-weighted) ----
    {
        const float* f1 = rank ? fpeer : fown;
        const float* f2 = rank ? fown : fpeer;
        int c = t >> 2, rq = t & 3;
        float f1c = f1[c];
        float mx = -3.0e38f;
        for (int r = rq * 16; r < rq * 16 + 16; r++) {
            int cnt = (cw[(r * 64 + c) >> 1] >> ((c & 1) * 16)) & 0xffff;
            if (cnt) mx = fmaxf(mx, leaky(f1c + f2[r]));
        }
        red[t] = mx; __syncthreads();
        mx = fmaxf(fmaxf(red[c * 4], red[c * 4 + 1]), fmaxf(red[c * 4 + 2], red[c * 4 + 3]));
        __syncthreads();
        float dp = 0.0f;
        for (int r = rq * 16; r < rq * 16 + 16; r++) {
            int cnt = (cw[(r * 64 + c) >> 1] >> ((c & 1) * 16)) & 0xffff;
            float e = 0.0f;
            if (cnt) e = (float)cnt * expf(leaky(f1c + f2[r]) - mx);
            Ss[r * 64 + c] = e; dp += e;
        }
        red[t] = dp; __syncthreads();
        float inv = 1.0f / (red[c * 4] + red[c * 4 + 1] + red[c * 4 + 2] + red[c * 4 + 3]);
        for (int r = rq * 16; r < rq * 16 + 16; r++) Ss[r * 64 + c] *= inv;
        __syncthreads();
    }

    // ---- stage 4: agg = S^T x -> Ab ; xc = mean_h leaky(x + agg @ lW[h]) ----
    {
        unsigned long long acc[8][2];
        #pragma unroll
        for (int r = 0; r < 8; r++) { acc[r][0] = 0ull; acc[r][1] = 0ull; }
        gsegT(Ss, xs, 128, 64, ty, txc, acc);
        estore<0>(Ab, 128, ty, txc, acc);
    }
    __syncthreads();
    {
        unsigned long long a0[8][2], a1[8][2];
        #pragma unroll
        for (int r = 0; r < 8; r++) { a0[r][0]=0ull;a0[r][1]=0ull;a1[r][0]=0ull;a1[r][1]=0ull; }
        gseg<128>(Ab, 128, lW,         128, ty, txc, a0);
        gseg<128>(Ab, 128, lW + 16384, 128, ty, txc, a1);
        #pragma unroll
        for (int r = 0; r < 8; r++) {
            int row = ty * 8 + r;
            #pragma unroll
            for (int j = 0; j < 2; j++) {
                float l0, h0, l1, h1v;
                unpackf2(a0[r][j], l0, h0);
                unpackf2(a1[r][j], l1, h1v);
                int col = txc * 4 + 2 * j;
                float x0 = xs[row * 128 + col], x1 = xs[row * 128 + col + 1];
                float vlo = 0.5f * (leaky(x0 + l0) + leaky(x0 + l1));
                float vhi = 0.5f * (leaky(x1 + h0) + leaky(x1 + h1v));
                *(float2*)(xs + row * 128 + col) = make_float2(vlo, vhi);  // x -> xc in place
            }
        }
    }
    __syncthreads();

    // ---- stage 5: q2 = hop2(xc) for rank0 (rank1 keeps qt in qs) ----
    if (rank == 0) {
        unsigned long long acc[8][2];
        #pragma unroll
        for (int r = 0; r < 8; r++) { acc[r][0] = 0ull; acc[r][1] = 0ull; }
        gseg<64>(Ms, 64, xs, 128, ty, txc, acc);
        estore<0>(Ab, 128, ty, txc, acc);
        __syncthreads();
        unsigned long long acc2[8][2];
        #pragma unroll
        for (int r = 0; r < 8; r++) { acc2[r][0] = 0ull; acc2[r][1] = 0ull; }
        gseg<64>(Ms, 64, Ab, 128, ty, txc, acc2);
        estore<0>(qs, 128, ty, txc, acc2);
        __syncthreads();
    }

    // ---- stage 6: attention #2 (head = 2 + rank), kv = xc -> gown ----
    attention(sm, t, ty, txc, xs, qs, 2 + (int)rank, Wk, W2, W3, gown);

    cluster_sync();
    if (t < 64) gpeer[t] = dsread(gown + t, rank ^ 1);
    __syncthreads();

    // ---- stage 7: cluster score softmax + top-52 ----
    if (t < 64) sscore[t] = gown[t] + gpeer[t];
    __syncthreads();
    softmax64(sscore, red, t);
    if (t < 32) {
        float v0 = sscore[t], v1 = sscore[t + 32];
        for (int j = 0; j < KK; j++) {
            float mv = v0; int mi = t;
            if (v1 > mv) { mv = v1; mi = t + 32; }
            #pragma unroll
            for (int off = 16; off; off >>= 1) {
                float ov = __shfl_xor_sync(0xffffffffu, mv, off);
                int   oi = __shfl_xor_sync(0xffffffffu, mi, off);
                if (ov > mv || (ov == mv && oi < mi)) { mv = ov; mi = oi; }
            }
            if (t == 0) permsh[j] = mi;
            if (mi < 32) { if (t == mi) v0 = -3.0e38f; }
            else         { if (t == mi - 32) v1 = -3.0e38f; }
        }
    }
    __syncthreads();

    // ---- stage 8: outputs ----
    if (rank == 0) {
        // x_out: re-read x from global (xs now holds xc)
        for (int i = t; i < KK * 32; i += NTHR) {
            int e = i >> 5, c4 = (i & 31) * 4;
            int p = permsh[e];
            float sc = sscore[p];
            float4 xv = *(const float4*)(xg + (size_t)b * 8192 + p * 128 + c4);
            *(float4*)(outx + (size_t)(b * KK + e) * 128 + c4) =
                make_float4(xv.x * sc, xv.y * sc, xv.z * sc, xv.w * sc);
        }
        if (t < KK) {
            int p = permsh[t];
            outb[b * KK + t] = (float)b;
            outp[b * KK + t] = (float)(b * 64 + p);
        }
    }

    // A2 block: T = A_d @ S_sel (in Ab); A2 rows split by rank
    float* T = Ab;   // 64*52 floats
    __syncthreads();
    for (int i = t; i < 64 * KK; i += NTHR) {
        int r = i / KK, j = i - r * KK;
        int cj = permsh[j];
        float acc = 0.0f;
        #pragma unroll
        for (int c = 0; c < 64; c++) acc += Ms[c * 64 + r] * Ss[c * 64 + cj];
        T[i] = acc;
    }
    __syncthreads();
    for (int o = t; o < 26 * KK; o += NTHR) {
        int il = o / KK, j = o - il * KK;
        int i = (int)rank * 26 + il;
        float v;
        if (i == j) v = 1.0f;
        else {
            int ci = permsh[i];
            v = 0.0f;
            #pragma unroll
            for (int r = 0; r < 64; r++) v += Ss[r * 64 + ci] * T[r * KK + j];
        }
        outA2[(size_t)(b * KK + i) * NK + (size_t)(b * KK + j)] = v;
    }
}

// =======================================================================
extern "C" void kernel_launch(void* const* d_in, const int* in_sizes, int n_in,
                              void* d_out, int out_size) {
    const float* x   = (const float*)d_in[0];
    const int*   ei  = (const int*)d_in[1];
    const float* ewt = (const float*)d_in[2];
    const float* tx  = (const float*)d_in[3];
    const float* Wk  = (const float*)d_in[5];
    const float* W1  = (const float*)d_in[6];
    const float* W2  = (const float*)d_in[7];
    const float* W3  = (const float*)d_in[8];
    const float* lW  = (const float*)d_in[9];
    float* out = (float*)d_out;

    float* out_x    = out;
    float* out_A2   = out + (size_t)NK * HH;
    float* out_bat  = out + (size_t)NK * HH + (size_t)NK * NK;
    float* out_perm = out_bat + NK;

    cudaFuncSetAttribute(mega_k, cudaFuncAttributeMaxDynamicSharedMemorySize, SM_BYTES);

    fold_k<<<(4 * 384 * 256 + 255) / 256, 256>>>(W1);
    mega_k<<<2 * BB, NTHR, SM_BYTES>>>(x, ei, ewt, tx, Wk, W2, W3, lW,
                                       out_x, out_A2, out_bat, out_perm);
}